// round 7
// baseline (speedup 1.0000x reference)
#include <cuda_runtime.h>
#include <cuda_fp16.h>
#include <cstdint>

#define NIMG 64
#define DIM  256
#define HW   1024
#define MTOT 65536
#define KCODES 1024
#define ZQ_ELEMS 16777216

__device__ float  g_enorm[KCODES];
__device__ int    g_idx[MTOT];
__device__ int    g_cand[MTOT * 4];
__device__ double g_loss;
__device__ __half g_ehi[KCODES * DIM];   // fp16(1024*emb)

// ---------------- smem layout (bytes), M-tile = 64, 4 E buffers ----------------
#define ZH_OFF 0                  // 64 rows x 264 halves (528B stride) = 33792
#define EB_OFF 33792              // 4 x (128 codes x 72 halves, 144B stride)
#define EB_SZ  18432              // ends at 107520
#define EN_OFF 107520             // 1024 f32 -> 111616
#define ZN_OFF 111616             // 64 f32  -> 111872
#define SMEM_ARG 111872
// aliased (E buffers are dead at these times):
#define CAND_OFF EB_OFF                     // 64 rows x 4 wn x 4 u64 = 8192 (after main loop)
#define TMP_OFF  (EB_OFF + 3*EB_SZ)         // 256 f32 (phase 1 only; buf3 written later)

__device__ __forceinline__ uint32_t smem_u32(const void* p) {
    uint32_t a;
    asm("{ .reg .u64 t; cvta.to.shared.u64 t, %1; cvt.u32.u64 %0, t; }" : "=r"(a) : "l"(p));
    return a;
}
#define LDSM4(r0,r1,r2,r3,addr) \
    asm volatile("ldmatrix.sync.aligned.m8n8.x4.shared.b16 {%0,%1,%2,%3}, [%4];" \
                 : "=r"(r0), "=r"(r1), "=r"(r2), "=r"(r3) : "r"(addr))
#define MMA_F16(c, a0,a1,a2,a3, b0,b1) \
    asm volatile("mma.sync.aligned.m16n8k16.row.col.f32.f16.f16.f32 " \
                 "{%0,%1,%2,%3}, {%4,%5,%6,%7}, {%8,%9}, {%0,%1,%2,%3};" \
                 : "+f"((c)[0]), "+f"((c)[1]), "+f"((c)[2]), "+f"((c)[3]) \
                 : "r"(a0), "r"(a1), "r"(a2), "r"(a3), "r"(b0), "r"(b1))

// sorted insert into ascending length-4 u64 list; early-reject fast path.
// pack = (f32bits(dist) << 32) | idx ; dist > 0 always (~256) so unsigned
// u64 order == (dist, idx) lexicographic order.
__device__ __forceinline__ void ins4u(unsigned long long* t, unsigned long long p) {
    if (p < t[3]) {
        t[3] = p;
        if (t[3] < t[2]) { unsigned long long x = t[2]; t[2] = t[3]; t[3] = x; }
        if (t[2] < t[1]) { unsigned long long x = t[1]; t[1] = t[2]; t[2] = x; }
        if (t[1] < t[0]) { unsigned long long x = t[0]; t[0] = t[1]; t[1] = x; }
    }
}

// ==================== small kernels ====================
__global__ void k_init() { g_loss = 0.0; }

// identical to round-1 (bit-matching enorm values, used by exact rescore)
__global__ void k_enorm(const float* __restrict__ emb) {
    int k = blockIdx.x, lid = threadIdx.x;
    const float* p = emb + (size_t)k * DIM + lid * 8;
    float4 a = *(const float4*)p;
    float4 b = *(const float4*)(p + 4);
    float s = a.x*a.x; s = fmaf(a.y,a.y,s); s = fmaf(a.z,a.z,s); s = fmaf(a.w,a.w,s);
    s = fmaf(b.x,b.x,s); s = fmaf(b.y,b.y,s); s = fmaf(b.z,b.z,s); s = fmaf(b.w,b.w,s);
    #pragma unroll
    for (int off = 16; off; off >>= 1) s += __shfl_xor_sync(0xffffffffu, s, off);
    if (lid == 0) g_enorm[k] = s;
}

__global__ void k_esplit(const float* __restrict__ emb) {
    int t = blockIdx.x * 256 + threadIdx.x;
    #pragma unroll
    for (int i = 0; i < 4; i++) {
        int id = t * 4 + i;
        g_ehi[id] = __float2half_rn(emb[id] * 1024.0f);
    }
}

// ==================== phase A: top-4 candidate search, single-term fp16 MMA ====================
__global__ void __launch_bounds__(256, 2)
k_argmin_mma(const float* __restrict__ z) {
    extern __shared__ char smem[];
    const uint32_t sb = smem_u32(smem);
    const int tid = threadIdx.x;
    const int lane = tid & 31;
    const int warp = tid >> 5;
    const int wm = warp & 1;        // rows wm*32..+31
    const int wn = warp >> 1;       // cols wn*32..+31 within 128-code tile

    const int m0 = blockIdx.x * 64;
    const int n_img = m0 >> 10;
    const int hw0 = m0 & (HW - 1);

    // ---- per-thread loader offsets (invariant across chunks) ----
    uint32_t dsto[4]; uint64_t srco[4];
    {
        const uint64_t ebase = (uint64_t)__cvta_generic_to_global(g_ehi);
        #pragma unroll
        for (int i = 0; i < 4; i++) {
            int g = tid * 4 + i;
            int code = g >> 3, u = g & 7;
            dsto[i] = (uint32_t)(code * 144 + u * 16);
            srco[i] = ebase + (uint64_t)(code * 512 + u * 16);
        }
    }
    // issue chunk j: codes [ (j>>2)*128, +128 ), k-halves [ (j&3)*64, +64 )
    auto issue_chunk = [&](int j) {
        const uint32_t dstb = sb + EB_OFF + (uint32_t)(j & 3) * EB_SZ;
        const uint64_t srcb = (uint64_t)((j >> 2) * 65536 + (j & 3) * 128);
        #pragma unroll
        for (int i = 0; i < 4; i++) {
            asm volatile("cp.async.cg.shared.global [%0], [%1], 16;"
                         :: "r"(dstb + dsto[i]), "l"(srco[i] + srcb) : "memory");
        }
        asm volatile("cp.async.commit_group;" ::: "memory");
    };

    issue_chunk(0); issue_chunk(1); issue_chunk(2);

    // ---------- phase 1: z load + fp16 + approx znorm; stage enorm ----------
    const float* zbase = z + (size_t)n_img * DIM * HW + hw0;
    {
        const int row = tid & 63;
        const int d0  = tid >> 6;          // 0..3
        __half* zh = (__half*)(smem + ZH_OFF);
        float zn = 0.f;
        #pragma unroll 8
        for (int i = 0; i < 64; i++) {
            int d = 4 * i + d0;
            float v = zbase[((size_t)d << 10) + row];
            zn = fmaf(v, v, zn);
            zh[row * 264 + d] = __float2half_rn(v);
        }
        float* tmp = (float*)(smem + TMP_OFF);
        tmp[tid] = zn;
        float* se = (float*)(smem + EN_OFF);
        #pragma unroll
        for (int i = 0; i < 4; i++) se[tid + 256 * i] = g_enorm[tid + 256 * i];
        __syncthreads();
        if (tid < 64)
            ((float*)(smem + ZN_OFF))[tid] = (tmp[tid] + tmp[tid + 64])
                                           + (tmp[tid + 128] + tmp[tid + 192]);
        __syncthreads();
    }

    // preload znorm + loop-invariant epilogue constants into registers
    float znreg[2][2];
    #pragma unroll
    for (int mt = 0; mt < 2; mt++)
        #pragma unroll
        for (int h = 0; h < 2; h++)
            znreg[mt][h] = ((const float*)(smem + ZN_OFF))
                           [wm * 32 + mt * 16 + h * 8 + (lane >> 2)];
    int collo[8];
    #pragma unroll
    for (int q = 0; q < 4; q++)
        #pragma unroll
        for (int c = 0; c < 2; c++)
            collo[q * 2 + c] = wn * 32 + q * 8 + (lane & 3) * 2 + c;

    // ---------- phase 2: main loop (32 chunks) ----------
    float acc[2][4][4];
    unsigned long long top[2][2][4];
    #pragma unroll
    for (int a = 0; a < 2; a++)
        #pragma unroll
        for (int b = 0; b < 2; b++)
            #pragma unroll
            for (int k = 0; k < 4; k++) top[a][b][k] = ~0ull;

    const float* s_en = (const float*)(smem + EN_OFF);

    for (int j = 0; j < 32; j++) {
        const int nt = j >> 2, kc = j & 3;

        if (j < 30)      asm volatile("cp.async.wait_group 2;" ::: "memory");
        else if (j == 30) asm volatile("cp.async.wait_group 1;" ::: "memory");
        else             asm volatile("cp.async.wait_group 0;" ::: "memory");
        __syncthreads();
        if (j + 3 < 32) issue_chunk(j + 3);

        if (kc == 0) {
            #pragma unroll
            for (int mt = 0; mt < 2; mt++)
                #pragma unroll
                for (int q = 0; q < 4; q++)
                    #pragma unroll
                    for (int c = 0; c < 4; c++) acc[mt][q][c] = 0.f;
        }

        const uint32_t abase = sb + ZH_OFF;
        const uint32_t bbase = sb + EB_OFF + (uint32_t)(j & 3) * EB_SZ;
        const uint32_t arow  = (uint32_t)(wm * 32 + (lane & 15)) * 528u;
        const uint32_t alanec = (uint32_t)((lane >> 4) * 16);
        const uint32_t brow0 = (uint32_t)(wn * 32 + (lane & 15)) * 144u;
        #pragma unroll
        for (int ks = 0; ks < 4; ks++) {
            const uint32_t akb = (uint32_t)(kc * 128 + ks * 32) + alanec;
            uint32_t a0[4], a1[4];
            LDSM4(a0[0],a0[1],a0[2],a0[3], abase + arow + akb);
            LDSM4(a1[0],a1[1],a1[2],a1[3], abase + arow + 16u*528u + akb);
            const uint32_t bkb = (uint32_t)(ks * 32) + alanec;
            uint32_t br[2][4];
            LDSM4(br[0][0],br[0][1],br[0][2],br[0][3], bbase + brow0 + bkb);
            LDSM4(br[1][0],br[1][1],br[1][2],br[1][3], bbase + brow0 + 16u*144u + bkb);
            #pragma unroll
            for (int qq = 0; qq < 2; qq++) {
                MMA_F16(acc[0][2*qq],   a0[0],a0[1],a0[2],a0[3], br[qq][0], br[qq][2]);
                MMA_F16(acc[0][2*qq+1], a0[0],a0[1],a0[2],a0[3], br[qq][1], br[qq][3]);
                MMA_F16(acc[1][2*qq],   a1[0],a1[1],a1[2],a1[3], br[qq][0], br[qq][2]);
                MMA_F16(acc[1][2*qq+1], a1[0],a1[1],a1[2],a1[3], br[qq][1], br[qq][3]);
            }
        }

        if (kc == 3) {
            // fused epilogue: top-4 per owned row; acc = 1024*dot, 2*dot = acc/512
            float enq[8];
            #pragma unroll
            for (int e = 0; e < 8; e++) enq[e] = s_en[nt * 128 + collo[e]];
            #pragma unroll
            for (int mt = 0; mt < 2; mt++) {
                #pragma unroll
                for (int h = 0; h < 2; h++) {
                    const float zn = znreg[mt][h];
                    #pragma unroll
                    for (int q = 0; q < 4; q++) {
                        #pragma unroll
                        for (int c = 0; c < 2; c++) {
                            const float dist = fmaf(acc[mt][q][2*h + c], -(1.0f/512.0f),
                                                    zn + enq[q*2 + c]);
                            const unsigned long long p =
                                ((unsigned long long)__float_as_uint(dist) << 32)
                                | (unsigned)(nt * 128 + collo[q*2 + c]);
                            ins4u(&top[mt][h][0], p);
                        }
                    }
                }
            }
        }
    }

    // ---------- candidate merge ----------
    #pragma unroll
    for (int mt = 0; mt < 2; mt++)
        #pragma unroll
        for (int h = 0; h < 2; h++) {
            #pragma unroll
            for (int off = 1; off <= 2; off <<= 1) {
                unsigned long long o[4];
                #pragma unroll
                for (int k = 0; k < 4; k++)
                    o[k] = __shfl_xor_sync(0xffffffffu, top[mt][h][k], off);
                #pragma unroll
                for (int k = 0; k < 4; k++) ins4u(&top[mt][h][0], o[k]);
            }
        }

    unsigned long long* cand = (unsigned long long*)(smem + CAND_OFF);
    __syncthreads();   // all LDSM reads of EB done -> safe to alias
    if ((lane & 3) == 0) {
        #pragma unroll
        for (int mt = 0; mt < 2; mt++)
            #pragma unroll
            for (int h = 0; h < 2; h++) {
                int row = wm * 32 + mt * 16 + h * 8 + (lane >> 2);
                #pragma unroll
                for (int k = 0; k < 4; k++)
                    cand[(row * 4 + wn) * 4 + k] = top[mt][h][k];
            }
    }
    __syncthreads();
    if (wn == 0 && (lane & 3) == 0) {
        #pragma unroll
        for (int mt = 0; mt < 2; mt++)
            #pragma unroll
            for (int h = 0; h < 2; h++) {
                int row = wm * 32 + mt * 16 + h * 8 + (lane >> 2);
                #pragma unroll
                for (int w2 = 1; w2 < 4; w2++)
                    #pragma unroll
                    for (int k = 0; k < 4; k++)
                        ins4u(&top[mt][h][0], cand[(row * 4 + w2) * 4 + k]);
                #pragma unroll
                for (int k = 0; k < 4; k++)
                    g_cand[(m0 + row) * 4 + k] = (int)(unsigned)(top[mt][h][k] & 0xffffffffull);
            }
    }
}

// ==================== phase B: exact fp32 rescore (round-1 bit-exact formulation) ====================
__global__ void __launch_bounds__(256)
k_exact(const float* __restrict__ z, const float* __restrict__ emb,
        float* __restrict__ out_idx) {
    int row = blockIdx.x * 256 + threadIdx.x;
    int n_img = row >> 10, hw = row & 1023;
    const float* zp = z + (size_t)n_img * DIM * HW + hw;

    int4 cn = *(const int4*)&g_cand[row * 4];
    const float4* e0 = (const float4*)(emb + ((size_t)cn.x << 8));
    const float4* e1 = (const float4*)(emb + ((size_t)cn.y << 8));
    const float4* e2 = (const float4*)(emb + ((size_t)cn.z << 8));
    const float4* e3 = (const float4*)(emb + ((size_t)cn.w << 8));

    float a0 = 0.f, a1 = 0.f, a2 = 0.f, a3 = 0.f, zn = 0.f;
    #pragma unroll 4
    for (int d4 = 0; d4 < 64; d4++) {
        float4 v0 = e0[d4], v1 = e1[d4], v2 = e2[d4], v3 = e3[d4];
        float zv;
        zv = zp[(size_t)(d4*4 + 0) << 10];
        zn = fmaf(zv, zv, zn);
        a0 = fmaf(zv, v0.x, a0); a1 = fmaf(zv, v1.x, a1);
        a2 = fmaf(zv, v2.x, a2); a3 = fmaf(zv, v3.x, a3);
        zv = zp[(size_t)(d4*4 + 1) << 10];
        zn = fmaf(zv, zv, zn);
        a0 = fmaf(zv, v0.y, a0); a1 = fmaf(zv, v1.y, a1);
        a2 = fmaf(zv, v2.y, a2); a3 = fmaf(zv, v3.y, a3);
        zv = zp[(size_t)(d4*4 + 2) << 10];
        zn = fmaf(zv, zv, zn);
        a0 = fmaf(zv, v0.z, a0); a1 = fmaf(zv, v1.z, a1);
        a2 = fmaf(zv, v2.z, a2); a3 = fmaf(zv, v3.z, a3);
        zv = zp[(size_t)(d4*4 + 3) << 10];
        zn = fmaf(zv, zv, zn);
        a0 = fmaf(zv, v0.w, a0); a1 = fmaf(zv, v1.w, a1);
        a2 = fmaf(zv, v2.w, a2); a3 = fmaf(zv, v3.w, a3);
    }

    float bd; int bi;
    {
        float t = zn - 2.0f * a0; bd = t + g_enorm[cn.x]; bi = cn.x;
    }
    {
        float t = zn - 2.0f * a1; float d = t + g_enorm[cn.y];
        if (d < bd || (d == bd && cn.y < bi)) { bd = d; bi = cn.y; }
    }
    {
        float t = zn - 2.0f * a2; float d = t + g_enorm[cn.z];
        if (d < bd || (d == bd && cn.z < bi)) { bd = d; bi = cn.z; }
    }
    {
        float t = zn - 2.0f * a3; float d = t + g_enorm[cn.w];
        if (d < bd || (d == bd && cn.w < bi)) { bd = d; bi = cn.w; }
    }

    g_idx[row]   = bi;
    out_idx[row] = (float)bi;
}

// ==================== output + loss ====================
__global__ void __launch_bounds__(256)
k_out(const float* __restrict__ z, const float* __restrict__ emb,
      float* __restrict__ out_zq) {
    int t    = blockIdx.x * 256 + threadIdx.x;
    int hw   = t & 1023;
    int rest = t >> 10;
    int db   = (rest & 63) << 2;
    int n    = rest >> 6;

    int idx = g_idx[(n << 10) + hw];
    float4 e = *(const float4*)&emb[(size_t)idx * DIM + db];

    size_t zb = (((size_t)n * DIM + db) << 10) + hw;
    float z0 = z[zb], z1 = z[zb + 1024], z2 = z[zb + 2048], z3 = z[zb + 3072];

    out_zq[zb]        = z0 + (e.x - z0);
    out_zq[zb + 1024] = z1 + (e.y - z1);
    out_zq[zb + 2048] = z2 + (e.z - z2);
    out_zq[zb + 3072] = z3 + (e.w - z3);

    float d0 = z0 - e.x, d1 = z1 - e.y, d2 = z2 - e.z, d3 = z3 - e.w;
    float sq = d0*d0 + d1*d1 + d2*d2 + d3*d3;

    #pragma unroll
    for (int off = 16; off; off >>= 1) sq += __shfl_xor_sync(0xffffffffu, sq, off);

    __shared__ float wsum[8];
    int wid = threadIdx.x >> 5, lid = threadIdx.x & 31;
    if (lid == 0) wsum[wid] = sq;
    __syncthreads();
    if (threadIdx.x == 0) {
        float s = 0.f;
        #pragma unroll
        for (int w = 0; w < 8; w++) s += wsum[w];
        atomicAdd(&g_loss, (double)s);
    }
}

__global__ void k_fin(float* __restrict__ out_loss) {
    float m = (float)(g_loss / (double)ZQ_ELEMS);
    out_loss[0] = 0.02f * m + m;
}

extern "C" void kernel_launch(void* const* d_in, const int* in_sizes, int n_in,
                              void* d_out, int out_size) {
    const float* z   = (const float*)d_in[0];
    const float* emb = (const float*)d_in[1];
    float* out      = (float*)d_out;
    float* out_zq   = out;
    float* out_idx  = out + ZQ_ELEMS;
    float* out_loss = out + ZQ_ELEMS + MTOT;

    cudaFuncSetAttribute(k_argmin_mma, cudaFuncAttributeMaxDynamicSharedMemorySize, SMEM_ARG);

    k_init      <<<1, 1>>>();
    k_enorm     <<<KCODES, 32>>>(emb);
    k_esplit    <<<256, 256>>>(emb);
    k_argmin_mma<<<MTOT / 64, 256, SMEM_ARG>>>(z);
    k_exact     <<<MTOT / 256, 256>>>(z, emb, out_idx);
    k_out       <<<ZQ_ELEMS / (256 * 4), 256>>>(z, emb, out_zq);
    k_fin       <<<1, 1>>>(out_loss);
}

// round 8
// speedup vs baseline: 1.8968x; 1.8968x over previous
#include <cuda_runtime.h>
#include <cuda_fp16.h>
#include <cstdint>

#define NIMG 64
#define DIM  256
#define HW   1024
#define MTOT 65536
#define KCODES 1024
#define ZQ_ELEMS 16777216

__device__ float  g_enorm[KCODES];
__device__ int    g_idx[MTOT];
__device__ int    g_cand[MTOT * 4];
__device__ double g_loss;
__device__ __half g_ehi[KCODES * DIM];   // fp16(1024*emb)

// ---------------- smem layout (bytes), M-tile = 64, 4 E buffers ----------------
#define ZH_OFF 0                  // 64 rows x 264 halves (528B stride) = 33792
#define EB_OFF 33792              // 4 x (128 codes x 72 halves, 144B stride)
#define EB_SZ  18432              // ends at 107520
#define EN_OFF 107520             // 1024 f32 (enorm + 0.5) -> 111616
#define SMEM_ARG 111616
// aliased after main loop (E buffers dead): 64 rows x 4 wn x 4 u32 = 4096
#define CAND_OFF EB_OFF

__device__ __forceinline__ uint32_t smem_u32(const void* p) {
    uint32_t a;
    asm("{ .reg .u64 t; cvta.to.shared.u64 t, %1; cvt.u32.u64 %0, t; }" : "=r"(a) : "l"(p));
    return a;
}
#define LDSM4(r0,r1,r2,r3,addr) \
    asm volatile("ldmatrix.sync.aligned.m8n8.x4.shared.b16 {%0,%1,%2,%3}, [%4];" \
                 : "=r"(r0), "=r"(r1), "=r"(r2), "=r"(r3) : "r"(addr))
#define MMA_F16(c, a0,a1,a2,a3, b0,b1) \
    asm volatile("mma.sync.aligned.m16n8k16.row.col.f32.f16.f16.f32 " \
                 "{%0,%1,%2,%3}, {%4,%5,%6,%7}, {%8,%9}, {%0,%1,%2,%3};" \
                 : "+f"((c)[0]), "+f"((c)[1]), "+f"((c)[2]), "+f"((c)[3]) \
                 : "r"(a0), "r"(a1), "r"(a2), "r"(a3), "r"(b0), "r"(b1))

// insert p into ascending 4-list (7 IMNMX, branchless) — used only in merges
__device__ __forceinline__ void ins4b(uint32_t* t, uint32_t p) {
    uint32_t c;
    c = umax(t[0], p); t[0] = umin(t[0], p);
    p = c;
    c = umax(t[1], p); t[1] = umin(t[1], p);
    p = c;
    c = umax(t[2], p); t[2] = umin(t[2], p);
    t[3] = umin(t[3], c);
}

// ==================== small kernels ====================
__global__ void k_init() { g_loss = 0.0; }

// identical to round-1 (bit-matching enorm values, used by exact rescore)
__global__ void k_enorm(const float* __restrict__ emb) {
    int k = blockIdx.x, lid = threadIdx.x;
    const float* p = emb + (size_t)k * DIM + lid * 8;
    float4 a = *(const float4*)p;
    float4 b = *(const float4*)(p + 4);
    float s = a.x*a.x; s = fmaf(a.y,a.y,s); s = fmaf(a.z,a.z,s); s = fmaf(a.w,a.w,s);
    s = fmaf(b.x,b.x,s); s = fmaf(b.y,b.y,s); s = fmaf(b.z,b.z,s); s = fmaf(b.w,b.w,s);
    #pragma unroll
    for (int off = 16; off; off >>= 1) s += __shfl_xor_sync(0xffffffffu, s, off);
    if (lid == 0) g_enorm[k] = s;
}

__global__ void k_esplit(const float* __restrict__ emb) {
    int t = blockIdx.x * 256 + threadIdx.x;
    #pragma unroll
    for (int i = 0; i < 4; i++) {
        int id = t * 4 + i;
        g_ehi[id] = __float2half_rn(emb[id] * 1024.0f);
    }
}

// ==================== phase A: candidate search, single-term fp16 MMA ====================
__global__ void __launch_bounds__(256, 2)
k_argmin_mma(const float* __restrict__ z) {
    extern __shared__ char smem[];
    const uint32_t sb = smem_u32(smem);
    const int tid = threadIdx.x;
    const int lane = tid & 31;
    const int warp = tid >> 5;
    const int wm = warp & 1;        // rows wm*32..+31
    const int wn = warp >> 1;       // cols wn*32..+31 within 128-code tile

    const int m0 = blockIdx.x * 64;
    const int n_img = m0 >> 10;
    const int hw0 = m0 & (HW - 1);

    // ---- per-thread loader offsets (invariant across chunks) ----
    uint32_t dsto[4]; uint64_t srco[4];
    {
        const uint64_t ebase = (uint64_t)__cvta_generic_to_global(g_ehi);
        #pragma unroll
        for (int i = 0; i < 4; i++) {
            int g = tid * 4 + i;
            int code = g >> 3, u = g & 7;
            dsto[i] = (uint32_t)(code * 144 + u * 16);
            srco[i] = ebase + (uint64_t)(code * 512 + u * 16);
        }
    }
    auto issue_chunk = [&](int j) {
        const uint32_t dstb = sb + EB_OFF + (uint32_t)(j & 3) * EB_SZ;
        const uint64_t srcb = (uint64_t)((j >> 2) * 65536 + (j & 3) * 128);
        #pragma unroll
        for (int i = 0; i < 4; i++) {
            asm volatile("cp.async.cg.shared.global [%0], [%1], 16;"
                         :: "r"(dstb + dsto[i]), "l"(srco[i] + srcb) : "memory");
        }
        asm volatile("cp.async.commit_group;" ::: "memory");
    };

    issue_chunk(0); issue_chunk(1); issue_chunk(2);

    // ---------- phase 1: z load + fp16; stage enorm+0.5 ----------
    const float* zbase = z + (size_t)n_img * DIM * HW + hw0;
    {
        const int row = tid & 63;
        const int d0  = tid >> 6;          // 0..3
        __half* zh = (__half*)(smem + ZH_OFF);
        #pragma unroll 8
        for (int i = 0; i < 64; i++) {
            int d = 4 * i + d0;
            float v = zbase[((size_t)d << 10) + row];
            zh[row * 264 + d] = __float2half_rn(v);
        }
        float* se = (float*)(smem + EN_OFF);
        #pragma unroll
        for (int i = 0; i < 4; i++) se[tid + 256 * i] = g_enorm[tid + 256 * i] + 0.5f;
        __syncthreads();
    }

    // loop-invariant epilogue column offsets
    int collo[8];
    #pragma unroll
    for (int q = 0; q < 4; q++)
        #pragma unroll
        for (int c = 0; c < 2; c++)
            collo[q * 2 + c] = wn * 32 + q * 8 + (lane & 3) * 2 + c;

    // ---------- phase 2: main loop (32 chunks) ----------
    float acc[2][4][4];
    uint32_t top[2][2][2];            // per (mt,h): ascending top-2 packed u32
    #pragma unroll
    for (int a = 0; a < 2; a++)
        #pragma unroll
        for (int b = 0; b < 2; b++) { top[a][b][0] = 0xFFFFFFFFu; top[a][b][1] = 0xFFFFFFFFu; }

    const float* s_en = (const float*)(smem + EN_OFF);

    for (int j = 0; j < 32; j++) {
        const int nt = j >> 2, kc = j & 3;

        if (j < 30)       asm volatile("cp.async.wait_group 2;" ::: "memory");
        else if (j == 30) asm volatile("cp.async.wait_group 1;" ::: "memory");
        else              asm volatile("cp.async.wait_group 0;" ::: "memory");
        __syncthreads();
        if (j + 3 < 32) issue_chunk(j + 3);

        if (kc == 0) {
            #pragma unroll
            for (int mt = 0; mt < 2; mt++)
                #pragma unroll
                for (int q = 0; q < 4; q++)
                    #pragma unroll
                    for (int c = 0; c < 4; c++) acc[mt][q][c] = 0.f;
        }

        const uint32_t abase = sb + ZH_OFF;
        const uint32_t bbase = sb + EB_OFF + (uint32_t)(j & 3) * EB_SZ;
        const uint32_t arow  = (uint32_t)(wm * 32 + (lane & 15)) * 528u;
        const uint32_t alanec = (uint32_t)((lane >> 4) * 16);
        const uint32_t brow0 = (uint32_t)(wn * 32 + (lane & 15)) * 144u;
        #pragma unroll
        for (int ks = 0; ks < 4; ks++) {
            const uint32_t akb = (uint32_t)(kc * 128 + ks * 32) + alanec;
            uint32_t a0[4], a1[4];
            LDSM4(a0[0],a0[1],a0[2],a0[3], abase + arow + akb);
            LDSM4(a1[0],a1[1],a1[2],a1[3], abase + arow + 16u*528u + akb);
            const uint32_t bkb = (uint32_t)(ks * 32) + alanec;
            uint32_t br[2][4];
            LDSM4(br[0][0],br[0][1],br[0][2],br[0][3], bbase + brow0 + bkb);
            LDSM4(br[1][0],br[1][1],br[1][2],br[1][3], bbase + brow0 + 16u*144u + bkb);
            #pragma unroll
            for (int qq = 0; qq < 2; qq++) {
                MMA_F16(acc[0][2*qq],   a0[0],a0[1],a0[2],a0[3], br[qq][0], br[qq][2]);
                MMA_F16(acc[0][2*qq+1], a0[0],a0[1],a0[2],a0[3], br[qq][1], br[qq][3]);
                MMA_F16(acc[1][2*qq],   a1[0],a1[1],a1[2],a1[3], br[qq][0], br[qq][2]);
                MMA_F16(acc[1][2*qq+1], a1[0],a1[1],a1[2],a1[3], br[qq][1], br[qq][3]);
            }
        }

        if (kc == 3) {
            // branchless epilogue: v = 0.5 + ||e||^2 - 2*dot (row-constant zn dropped);
            // pack code index into low 10 mantissa bits; top-2 via 3 IMNMX.
            float enq[8]; uint32_t codes[8];
            #pragma unroll
            for (int e = 0; e < 8; e++) {
                enq[e]   = s_en[nt * 128 + collo[e]];
                codes[e] = (uint32_t)(nt * 128 + collo[e]);
            }
            #pragma unroll
            for (int mt = 0; mt < 2; mt++) {
                #pragma unroll
                for (int h = 0; h < 2; h++) {
                    #pragma unroll
                    for (int e = 0; e < 8; e++) {
                        const float v = fmaf(acc[mt][e >> 1][2*h + (e & 1)],
                                             -(1.0f/512.0f), enq[e]);
                        const uint32_t p = (__float_as_uint(v) & 0xFFFFFC00u) | codes[e];
                        const uint32_t t0 = top[mt][h][0];
                        const uint32_t cr = umax(t0, p);
                        top[mt][h][0] = umin(t0, p);
                        top[mt][h][1] = umin(top[mt][h][1], cr);
                    }
                }
            }
        }
    }

    // ---------- candidate merge (4-deep lists from here on) ----------
    uint32_t L[2][2][4];
    #pragma unroll
    for (int mt = 0; mt < 2; mt++)
        #pragma unroll
        for (int h = 0; h < 2; h++) {
            L[mt][h][0] = top[mt][h][0]; L[mt][h][1] = top[mt][h][1];
            L[mt][h][2] = 0xFFFFFFFFu;   L[mt][h][3] = 0xFFFFFFFFu;
            #pragma unroll
            for (int off = 1; off <= 2; off <<= 1) {
                uint32_t o[4];
                #pragma unroll
                for (int k = 0; k < 4; k++)
                    o[k] = __shfl_xor_sync(0xffffffffu, L[mt][h][k], off);
                #pragma unroll
                for (int k = 0; k < 4; k++) ins4b(&L[mt][h][0], o[k]);
            }
        }

    uint32_t* cand = (uint32_t*)(smem + CAND_OFF);
    __syncthreads();   // all LDSM reads of EB done -> safe to alias
    if ((lane & 3) == 0) {
        #pragma unroll
        for (int mt = 0; mt < 2; mt++)
            #pragma unroll
            for (int h = 0; h < 2; h++) {
                int row = wm * 32 + mt * 16 + h * 8 + (lane >> 2);
                #pragma unroll
                for (int k = 0; k < 4; k++)
                    cand[(row * 4 + wn) * 4 + k] = L[mt][h][k];
            }
    }
    __syncthreads();
    if (wn == 0 && (lane & 3) == 0) {
        #pragma unroll
        for (int mt = 0; mt < 2; mt++)
            #pragma unroll
            for (int h = 0; h < 2; h++) {
                int row = wm * 32 + mt * 16 + h * 8 + (lane >> 2);
                #pragma unroll
                for (int w2 = 1; w2 < 4; w2++)
                    #pragma unroll
                    for (int k = 0; k < 4; k++)
                        ins4b(&L[mt][h][0], cand[(row * 4 + w2) * 4 + k]);
                #pragma unroll
                for (int k = 0; k < 4; k++)
                    g_cand[(m0 + row) * 4 + k] = (int)(L[mt][h][k] & 1023u);
            }
    }
}

// ==================== phase B: exact fp32 rescore (round-1 bit-exact formulation) ====================
__global__ void __launch_bounds__(256)
k_exact(const float* __restrict__ z, const float* __restrict__ emb,
        float* __restrict__ out_idx) {
    int row = blockIdx.x * 256 + threadIdx.x;
    int n_img = row >> 10, hw = row & 1023;
    const float* zp = z + (size_t)n_img * DIM * HW + hw;

    int4 cn = *(const int4*)&g_cand[row * 4];
    const float4* e0 = (const float4*)(emb + ((size_t)cn.x << 8));
    const float4* e1 = (const float4*)(emb + ((size_t)cn.y << 8));
    const float4* e2 = (const float4*)(emb + ((size_t)cn.z << 8));
    const float4* e3 = (const float4*)(emb + ((size_t)cn.w << 8));

    float a0 = 0.f, a1 = 0.f, a2 = 0.f, a3 = 0.f, zn = 0.f;
    #pragma unroll 4
    for (int d4 = 0; d4 < 64; d4++) {
        float4 v0 = e0[d4], v1 = e1[d4], v2 = e2[d4], v3 = e3[d4];
        float zv;
        zv = zp[(size_t)(d4*4 + 0) << 10];
        zn = fmaf(zv, zv, zn);
        a0 = fmaf(zv, v0.x, a0); a1 = fmaf(zv, v1.x, a1);
        a2 = fmaf(zv, v2.x, a2); a3 = fmaf(zv, v3.x, a3);
        zv = zp[(size_t)(d4*4 + 1) << 10];
        zn = fmaf(zv, zv, zn);
        a0 = fmaf(zv, v0.y, a0); a1 = fmaf(zv, v1.y, a1);
        a2 = fmaf(zv, v2.y, a2); a3 = fmaf(zv, v3.y, a3);
        zv = zp[(size_t)(d4*4 + 2) << 10];
        zn = fmaf(zv, zv, zn);
        a0 = fmaf(zv, v0.z, a0); a1 = fmaf(zv, v1.z, a1);
        a2 = fmaf(zv, v2.z, a2); a3 = fmaf(zv, v3.z, a3);
        zv = zp[(size_t)(d4*4 + 3) << 10];
        zn = fmaf(zv, zv, zn);
        a0 = fmaf(zv, v0.w, a0); a1 = fmaf(zv, v1.w, a1);
        a2 = fmaf(zv, v2.w, a2); a3 = fmaf(zv, v3.w, a3);
    }

    float bd; int bi;
    {
        float t = zn - 2.0f * a0; bd = t + g_enorm[cn.x]; bi = cn.x;
    }
    {
        float t = zn - 2.0f * a1; float d = t + g_enorm[cn.y];
        if (d < bd || (d == bd && cn.y < bi)) { bd = d; bi = cn.y; }
    }
    {
        float t = zn - 2.0f * a2; float d = t + g_enorm[cn.z];
        if (d < bd || (d == bd && cn.z < bi)) { bd = d; bi = cn.z; }
    }
    {
        float t = zn - 2.0f * a3; float d = t + g_enorm[cn.w];
        if (d < bd || (d == bd && cn.w < bi)) { bd = d; bi = cn.w; }
    }

    g_idx[row]   = bi;
    out_idx[row] = (float)bi;
}

// ==================== output + loss ====================
__global__ void __launch_bounds__(256)
k_out(const float* __restrict__ z, const float* __restrict__ emb,
      float* __restrict__ out_zq) {
    int t    = blockIdx.x * 256 + threadIdx.x;
    int hw   = t & 1023;
    int rest = t >> 10;
    int db   = (rest & 63) << 2;
    int n    = rest >> 6;

    int idx = g_idx[(n << 10) + hw];
    float4 e = *(const float4*)&emb[(size_t)idx * DIM + db];

    size_t zb = (((size_t)n * DIM + db) << 10) + hw;
    float z0 = z[zb], z1 = z[zb + 1024], z2 = z[zb + 2048], z3 = z[zb + 3072];

    out_zq[zb]        = z0 + (e.x - z0);
    out_zq[zb + 1024] = z1 + (e.y - z1);
    out_zq[zb + 2048] = z2 + (e.z - z2);
    out_zq[zb + 3072] = z3 + (e.w - z3);

    float d0 = z0 - e.x, d1 = z1 - e.y, d2 = z2 - e.z, d3 = z3 - e.w;
    float sq = d0*d0 + d1*d1 + d2*d2 + d3*d3;

    #pragma unroll
    for (int off = 16; off; off >>= 1) sq += __shfl_xor_sync(0xffffffffu, sq, off);

    __shared__ float wsum[8];
    int wid = threadIdx.x >> 5, lid = threadIdx.x & 31;
    if (lid == 0) wsum[wid] = sq;
    __syncthreads();
    if (threadIdx.x == 0) {
        float s = 0.f;
        #pragma unroll
        for (int w = 0; w < 8; w++) s += wsum[w];
        atomicAdd(&g_loss, (double)s);
    }
}

__global__ void k_fin(float* __restrict__ out_loss) {
    float m = (float)(g_loss / (double)ZQ_ELEMS);
    out_loss[0] = 0.02f * m + m;
}

extern "C" void kernel_launch(void* const* d_in, const int* in_sizes, int n_in,
                              void* d_out, int out_size) {
    const float* z   = (const float*)d_in[0];
    const float* emb = (const float*)d_in[1];
    float* out      = (float*)d_out;
    float* out_zq   = out;
    float* out_idx  = out + ZQ_ELEMS;
    float* out_loss = out + ZQ_ELEMS + MTOT;

    cudaFuncSetAttribute(k_argmin_mma, cudaFuncAttributeMaxDynamicSharedMemorySize, SMEM_ARG);

    k_init      <<<1, 1>>>();
    k_enorm     <<<KCODES, 32>>>(emb);
    k_esplit    <<<256, 256>>>(emb);
    k_argmin_mma<<<MTOT / 64, 256, SMEM_ARG>>>(z);
    k_exact     <<<MTOT / 256, 256>>>(z, emb, out_idx);
    k_out       <<<ZQ_ELEMS / (256 * 4), 256>>>(z, emb, out_zq);
    k_fin       <<<1, 1>>>(out_loss);
}

// round 9
// speedup vs baseline: 1.9639x; 1.0354x over previous
#include <cuda_runtime.h>
#include <cuda_fp16.h>
#include <cstdint>

#define NIMG 64
#define DIM  256
#define HW   1024
#define MTOT 65536
#define KCODES 1024
#define ZQ_ELEMS 16777216

__device__ float  g_enorm[KCODES];
__device__ int    g_idx[MTOT];
__device__ double g_loss;
__device__ __half g_ehi[KCODES * DIM];   // fp16(1024*emb)

// ---------------- smem layout (bytes), M-tile = 128, 4 E buffers ----------------
#define ZH_OFF 0                  // 128 rows x 264 halves (528B stride) = 67584
#define EB_OFF 67584              // 4 x (128 codes x 72 halves, 144B stride)
#define EB_SZ  18432              // ends at 141312
#define EN_OFF 141312             // 1024 f32 (enorm + 0.5) -> 145408
#define SMEM_ARG 145408
// aliased after main loop (E buffers dead):
#define CAND_OFF  EB_OFF               // 128 rows x 4 wn x 4 u32 = 8192
#define CAND2_OFF (EB_OFF + 8192)      // 128 rows x 4 u32 merged = 2048

__device__ __forceinline__ uint32_t smem_u32(const void* p) {
    uint32_t a;
    asm("{ .reg .u64 t; cvta.to.shared.u64 t, %1; cvt.u32.u64 %0, t; }" : "=r"(a) : "l"(p));
    return a;
}
#define LDSM4(r0,r1,r2,r3,addr) \
    asm volatile("ldmatrix.sync.aligned.m8n8.x4.shared.b16 {%0,%1,%2,%3}, [%4];" \
                 : "=r"(r0), "=r"(r1), "=r"(r2), "=r"(r3) : "r"(addr))
#define MMA_F16(c, a0,a1,a2,a3, b0,b1) \
    asm volatile("mma.sync.aligned.m16n8k16.row.col.f32.f16.f16.f32 " \
                 "{%0,%1,%2,%3}, {%4,%5,%6,%7}, {%8,%9}, {%0,%1,%2,%3};" \
                 : "+f"((c)[0]), "+f"((c)[1]), "+f"((c)[2]), "+f"((c)[3]) \
                 : "r"(a0), "r"(a1), "r"(a2), "r"(a3), "r"(b0), "r"(b1))

// insert p into ascending 4-list (branchless IMNMX chain) — merges only
__device__ __forceinline__ void ins4b(uint32_t* t, uint32_t p) {
    uint32_t c;
    c = umax(t[0], p); t[0] = umin(t[0], p);
    p = c;
    c = umax(t[1], p); t[1] = umin(t[1], p);
    p = c;
    c = umax(t[2], p); t[2] = umin(t[2], p);
    t[3] = umin(t[3], c);
}

// ==================== small kernels ====================
__global__ void k_init() { g_loss = 0.0; }

// identical to round-1 (bit-matching enorm values, used by exact rescore)
__global__ void k_enorm(const float* __restrict__ emb) {
    int k = blockIdx.x, lid = threadIdx.x;
    const float* p = emb + (size_t)k * DIM + lid * 8;
    float4 a = *(const float4*)p;
    float4 b = *(const float4*)(p + 4);
    float s = a.x*a.x; s = fmaf(a.y,a.y,s); s = fmaf(a.z,a.z,s); s = fmaf(a.w,a.w,s);
    s = fmaf(b.x,b.x,s); s = fmaf(b.y,b.y,s); s = fmaf(b.z,b.z,s); s = fmaf(b.w,b.w,s);
    #pragma unroll
    for (int off = 16; off; off >>= 1) s += __shfl_xor_sync(0xffffffffu, s, off);
    if (lid == 0) g_enorm[k] = s;
}

__global__ void k_esplit(const float* __restrict__ emb) {
    int t = blockIdx.x * 256 + threadIdx.x;
    #pragma unroll
    for (int i = 0; i < 4; i++) {
        int id = t * 4 + i;
        g_ehi[id] = __float2half_rn(emb[id] * 1024.0f);
    }
}

// ==================== phase A+B: candidate search + fused exact rescore ====================
__global__ void __launch_bounds__(512, 1)
k_argmin_mma(const float* __restrict__ z, const float* __restrict__ emb,
             float* __restrict__ out_idx) {
    extern __shared__ char smem[];
    const uint32_t sb = smem_u32(smem);
    const int tid = threadIdx.x;
    const int lane = tid & 31;
    const int warp = tid >> 5;
    const int wm = warp & 3;        // rows wm*32..+31
    const int wn = warp >> 2;       // cols wn*32..+31 within 128-code tile

    const int m0 = blockIdx.x * 128;
    const int n_img = m0 >> 10;
    const int hw0 = m0 & (HW - 1);

    // ---- per-thread loader offsets (2 x 16B per thread per chunk) ----
    uint32_t dsto[2]; uint64_t srco[2];
    {
        const uint64_t ebase = (uint64_t)__cvta_generic_to_global(g_ehi);
        #pragma unroll
        for (int i = 0; i < 2; i++) {
            int g = tid * 2 + i;
            int code = g >> 3, u = g & 7;
            dsto[i] = (uint32_t)(code * 144 + u * 16);
            srco[i] = ebase + (uint64_t)(code * 512 + u * 16);
        }
    }
    auto issue_chunk = [&](int j) {
        const uint32_t dstb = sb + EB_OFF + (uint32_t)(j & 3) * EB_SZ;
        const uint64_t srcb = (uint64_t)((j >> 2) * 65536 + (j & 3) * 128);
        #pragma unroll
        for (int i = 0; i < 2; i++) {
            asm volatile("cp.async.cg.shared.global [%0], [%1], 16;"
                         :: "r"(dstb + dsto[i]), "l"(srco[i] + srcb) : "memory");
        }
        asm volatile("cp.async.commit_group;" ::: "memory");
    };

    issue_chunk(0); issue_chunk(1); issue_chunk(2);

    // ---------- phase 1: z load + fp16; stage enorm+0.5 ----------
    const float* zbase = z + (size_t)n_img * DIM * HW + hw0;
    {
        const int row = tid & 127;
        const int d0  = tid >> 7;          // 0..3
        __half* zh = (__half*)(smem + ZH_OFF);
        #pragma unroll 8
        for (int i = 0; i < 64; i++) {
            int d = 4 * i + d0;
            float v = zbase[((size_t)d << 10) + row];
            zh[row * 264 + d] = __float2half_rn(v);
        }
        float* se = (float*)(smem + EN_OFF);
        se[tid]       = g_enorm[tid]       + 0.5f;
        se[tid + 512] = g_enorm[tid + 512] + 0.5f;
        __syncthreads();
    }

    // loop-invariant epilogue column offsets
    int collo[8];
    #pragma unroll
    for (int q = 0; q < 4; q++)
        #pragma unroll
        for (int c = 0; c < 2; c++)
            collo[q * 2 + c] = wn * 32 + q * 8 + (lane & 3) * 2 + c;

    // ---------- phase 2: main loop (32 chunks) ----------
    float acc[2][4][4];
    uint32_t top[2][2][2];            // per (mt,h): ascending top-2 packed u32
    #pragma unroll
    for (int a = 0; a < 2; a++)
        #pragma unroll
        for (int b = 0; b < 2; b++) { top[a][b][0] = 0xFFFFFFFFu; top[a][b][1] = 0xFFFFFFFFu; }

    const float* s_en = (const float*)(smem + EN_OFF);

    for (int j = 0; j < 32; j++) {
        const int nt = j >> 2, kc = j & 3;

        if (j < 30)       asm volatile("cp.async.wait_group 2;" ::: "memory");
        else if (j == 30) asm volatile("cp.async.wait_group 1;" ::: "memory");
        else              asm volatile("cp.async.wait_group 0;" ::: "memory");
        __syncthreads();
        if (j + 3 < 32) issue_chunk(j + 3);

        if (kc == 0) {
            #pragma unroll
            for (int mt = 0; mt < 2; mt++)
                #pragma unroll
                for (int q = 0; q < 4; q++)
                    #pragma unroll
                    for (int c = 0; c < 4; c++) acc[mt][q][c] = 0.f;
        }

        const uint32_t abase = sb + ZH_OFF;
        const uint32_t bbase = sb + EB_OFF + (uint32_t)(j & 3) * EB_SZ;
        const uint32_t arow  = (uint32_t)(wm * 32 + (lane & 15)) * 528u;
        const uint32_t alanec = (uint32_t)((lane >> 4) * 16);
        const uint32_t brow0 = (uint32_t)(wn * 32 + (lane & 15)) * 144u;
        #pragma unroll
        for (int ks = 0; ks < 4; ks++) {
            const uint32_t akb = (uint32_t)(kc * 128 + ks * 32) + alanec;
            uint32_t a0[4], a1[4];
            LDSM4(a0[0],a0[1],a0[2],a0[3], abase + arow + akb);
            LDSM4(a1[0],a1[1],a1[2],a1[3], abase + arow + 16u*528u + akb);
            const uint32_t bkb = (uint32_t)(ks * 32) + alanec;
            uint32_t br[2][4];
            LDSM4(br[0][0],br[0][1],br[0][2],br[0][3], bbase + brow0 + bkb);
            LDSM4(br[1][0],br[1][1],br[1][2],br[1][3], bbase + brow0 + 16u*144u + bkb);
            #pragma unroll
            for (int qq = 0; qq < 2; qq++) {
                MMA_F16(acc[0][2*qq],   a0[0],a0[1],a0[2],a0[3], br[qq][0], br[qq][2]);
                MMA_F16(acc[0][2*qq+1], a0[0],a0[1],a0[2],a0[3], br[qq][1], br[qq][3]);
                MMA_F16(acc[1][2*qq],   a1[0],a1[1],a1[2],a1[3], br[qq][0], br[qq][2]);
                MMA_F16(acc[1][2*qq+1], a1[0],a1[1],a1[2],a1[3], br[qq][1], br[qq][3]);
            }
        }

        if (kc == 3) {
            // branchless epilogue: v = 0.5 + ||e||^2 - 2*dot; idx in low 10 mantissa bits
            float enq[8]; uint32_t codes[8];
            #pragma unroll
            for (int e = 0; e < 8; e++) {
                enq[e]   = s_en[nt * 128 + collo[e]];
                codes[e] = (uint32_t)(nt * 128 + collo[e]);
            }
            #pragma unroll
            for (int mt = 0; mt < 2; mt++) {
                #pragma unroll
                for (int h = 0; h < 2; h++) {
                    #pragma unroll
                    for (int e = 0; e < 8; e++) {
                        const float v = fmaf(acc[mt][e >> 1][2*h + (e & 1)],
                                             -(1.0f/512.0f), enq[e]);
                        const uint32_t p = (__float_as_uint(v) & 0xFFFFFC00u) | codes[e];
                        const uint32_t t0 = top[mt][h][0];
                        const uint32_t cr = umax(t0, p);
                        top[mt][h][0] = umin(t0, p);
                        top[mt][h][1] = umin(top[mt][h][1], cr);
                    }
                }
            }
        }
    }

    // ---------- candidate merge (4-deep lists from here on) ----------
    uint32_t L[2][2][4];
    #pragma unroll
    for (int mt = 0; mt < 2; mt++)
        #pragma unroll
        for (int h = 0; h < 2; h++) {
            L[mt][h][0] = top[mt][h][0]; L[mt][h][1] = top[mt][h][1];
            L[mt][h][2] = 0xFFFFFFFFu;   L[mt][h][3] = 0xFFFFFFFFu;
            #pragma unroll
            for (int off = 1; off <= 2; off <<= 1) {
                uint32_t o[4];
                #pragma unroll
                for (int k = 0; k < 4; k++)
                    o[k] = __shfl_xor_sync(0xffffffffu, L[mt][h][k], off);
                #pragma unroll
                for (int k = 0; k < 4; k++) ins4b(&L[mt][h][0], o[k]);
            }
        }

    uint32_t* cand  = (uint32_t*)(smem + CAND_OFF);
    uint32_t* cand2 = (uint32_t*)(smem + CAND2_OFF);
    __syncthreads();   // all LDSM reads of EB done -> safe to alias
    if ((lane & 3) == 0) {
        #pragma unroll
        for (int mt = 0; mt < 2; mt++)
            #pragma unroll
            for (int h = 0; h < 2; h++) {
                int row = wm * 32 + mt * 16 + h * 8 + (lane >> 2);
                #pragma unroll
                for (int k = 0; k < 4; k++)
                    cand[(row * 4 + wn) * 4 + k] = L[mt][h][k];
            }
    }
    __syncthreads();
    if (wn == 0 && (lane & 3) == 0) {
        #pragma unroll
        for (int mt = 0; mt < 2; mt++)
            #pragma unroll
            for (int h = 0; h < 2; h++) {
                int row = wm * 32 + mt * 16 + h * 8 + (lane >> 2);
                #pragma unroll
                for (int w2 = 1; w2 < 4; w2++)
                    #pragma unroll
                    for (int k = 0; k < 4; k++)
                        ins4b(&L[mt][h][0], cand[(row * 4 + w2) * 4 + k]);
                #pragma unroll
                for (int k = 0; k < 4; k++)
                    cand2[row * 4 + k] = L[mt][h][k] & 1023u;
            }
    }
    __syncthreads();

    // ---------- fused phase B: exact fp32 rescore (round-1 bit-exact formulation) ----------
    if (tid < 128) {
        const int row = m0 + tid;
        const float* zp = zbase + tid;

        int4 cn = *(const int4*)&cand2[tid * 4];
        const float4* e0 = (const float4*)(emb + ((size_t)cn.x << 8));
        const float4* e1 = (const float4*)(emb + ((size_t)cn.y << 8));
        const float4* e2 = (const float4*)(emb + ((size_t)cn.z << 8));
        const float4* e3 = (const float4*)(emb + ((size_t)cn.w << 8));

        float a0 = 0.f, a1 = 0.f, a2 = 0.f, a3 = 0.f, zn = 0.f;
        #pragma unroll 4
        for (int d4 = 0; d4 < 64; d4++) {
            float4 v0 = e0[d4], v1 = e1[d4], v2 = e2[d4], v3 = e3[d4];
            float zv;
            zv = zp[(size_t)(d4*4 + 0) << 10];
            zn = fmaf(zv, zv, zn);
            a0 = fmaf(zv, v0.x, a0); a1 = fmaf(zv, v1.x, a1);
            a2 = fmaf(zv, v2.x, a2); a3 = fmaf(zv, v3.x, a3);
            zv = zp[(size_t)(d4*4 + 1) << 10];
            zn = fmaf(zv, zv, zn);
            a0 = fmaf(zv, v0.y, a0); a1 = fmaf(zv, v1.y, a1);
            a2 = fmaf(zv, v2.y, a2); a3 = fmaf(zv, v3.y, a3);
            zv = zp[(size_t)(d4*4 + 2) << 10];
            zn = fmaf(zv, zv, zn);
            a0 = fmaf(zv, v0.z, a0); a1 = fmaf(zv, v1.z, a1);
            a2 = fmaf(zv, v2.z, a2); a3 = fmaf(zv, v3.z, a3);
            zv = zp[(size_t)(d4*4 + 3) << 10];
            zn = fmaf(zv, zv, zn);
            a0 = fmaf(zv, v0.w, a0); a1 = fmaf(zv, v1.w, a1);
            a2 = fmaf(zv, v2.w, a2); a3 = fmaf(zv, v3.w, a3);
        }

        float bd; int bi;
        {
            float t = zn - 2.0f * a0; bd = t + g_enorm[cn.x]; bi = cn.x;
        }
        {
            float t = zn - 2.0f * a1; float d = t + g_enorm[cn.y];
            if (d < bd || (d == bd && cn.y < bi)) { bd = d; bi = cn.y; }
        }
        {
            float t = zn - 2.0f * a2; float d = t + g_enorm[cn.z];
            if (d < bd || (d == bd && cn.z < bi)) { bd = d; bi = cn.z; }
        }
        {
            float t = zn - 2.0f * a3; float d = t + g_enorm[cn.w];
            if (d < bd || (d == bd && cn.w < bi)) { bd = d; bi = cn.w; }
        }

        g_idx[row]   = bi;
        out_idx[row] = (float)bi;
    }
}

// ==================== output + loss ====================
__global__ void __launch_bounds__(256)
k_out(const float* __restrict__ z, const float* __restrict__ emb,
      float* __restrict__ out_zq) {
    int t    = blockIdx.x * 256 + threadIdx.x;
    int hw   = t & 1023;
    int rest = t >> 10;
    int db   = (rest & 63) << 2;
    int n    = rest >> 6;

    int idx = g_idx[(n << 10) + hw];
    float4 e = *(const float4*)&emb[(size_t)idx * DIM + db];

    size_t zb = (((size_t)n * DIM + db) << 10) + hw;
    float z0 = z[zb], z1 = z[zb + 1024], z2 = z[zb + 2048], z3 = z[zb + 3072];

    out_zq[zb]        = z0 + (e.x - z0);
    out_zq[zb + 1024] = z1 + (e.y - z1);
    out_zq[zb + 2048] = z2 + (e.z - z2);
    out_zq[zb + 3072] = z3 + (e.w - z3);

    float d0 = z0 - e.x, d1 = z1 - e.y, d2 = z2 - e.z, d3 = z3 - e.w;
    float sq = d0*d0 + d1*d1 + d2*d2 + d3*d3;

    #pragma unroll
    for (int off = 16; off; off >>= 1) sq += __shfl_xor_sync(0xffffffffu, sq, off);

    __shared__ float wsum[8];
    int wid = threadIdx.x >> 5, lid = threadIdx.x & 31;
    if (lid == 0) wsum[wid] = sq;
    __syncthreads();
    if (threadIdx.x == 0) {
        float s = 0.f;
        #pragma unroll
        for (int w = 0; w < 8; w++) s += wsum[w];
        atomicAdd(&g_loss, (double)s);
    }
}

__global__ void k_fin(float* __restrict__ out_loss) {
    float m = (float)(g_loss / (double)ZQ_ELEMS);
    out_loss[0] = 0.02f * m + m;
}

extern "C" void kernel_launch(void* const* d_in, const int* in_sizes, int n_in,
                              void* d_out, int out_size) {
    const float* z   = (const float*)d_in[0];
    const float* emb = (const float*)d_in[1];
    float* out      = (float*)d_out;
    float* out_zq   = out;
    float* out_idx  = out + ZQ_ELEMS;
    float* out_loss = out + ZQ_ELEMS + MTOT;

    cudaFuncSetAttribute(k_argmin_mma, cudaFuncAttributeMaxDynamicSharedMemorySize, SMEM_ARG);

    k_init      <<<1, 1>>>();
    k_enorm     <<<KCODES, 32>>>(emb);
    k_esplit    <<<256, 256>>>(emb);
    k_argmin_mma<<<MTOT / 128, 512, SMEM_ARG>>>(z, emb, out_idx);
    k_out       <<<ZQ_ELEMS / (256 * 4), 256>>>(z, emb, out_zq);
    k_fin       <<<1, 1>>>(out_loss);
}